// round 13
// baseline (speedup 1.0000x reference)
#include <cuda_runtime.h>
#include <cuda_bf16.h>

// ---------------------------------------------------------------------------
// ResidualVectorQuantize (eval mode), fp32 faithful, f32x2-packed, v10.
// B=16, T=4096, D=512, N=9, K=1024, d=8.
// Output layout (float32): [z_q (B*T*D)] [codes (B*T*N)] [latents (B*T*N*d)]
//                          [commitment_loss] [codebook_loss]
// v10 = v7 math with ALL weight smem staging removed: weights/biases/codebook
//       read directly via LDG and served from L1D (228KB - ~6KB smem carveout
//       holds the full 144KB two-block working set). Deletes 9 LDGSTS/thread/
//       iter + CP_WAIT machinery (R10 measured that cost at ~100us).
// ---------------------------------------------------------------------------

typedef unsigned long long ull;

#define BT   65536
#define DDIM 512
#define KCB  1024
#define NCB  9

#define OFF_CODES 33554432ull
#define OFF_LAT   34144256ull
#define OFF_LOSS  38862848ull

#define THREADS    256
#define TOKPB      32                  // tokens per block (4 per warp)
#define NBLOCKS    (BT / TOKPB)        // 2048

// smem layout, ull units (tiny now):
#define U_ENCD   0                     // ull[320]: enc dup'd, stride 10/token
#define U_CAND   320                   // ull[288]: stride 9/token
#define U_TOTAL  608
#define F_ZQ     (U_TOTAL * 2)         // float[256]: ze then zq, stride 8/token
#define F_LOSS   (F_ZQ + 256)          // float[8]
#define SMEM_BYTES ((F_LOSS + 8) * 4)  // 5920

// -------------------------- device scratch --------------------------------
__device__ double   g_loss = 0.0;
__device__ unsigned g_done = 0;
__device__ float4 g_Win4 [NCB * 1024];  // interleaved: [i*1024+dim], [..+512+dim]
__device__ float4 g_Wout4[NCB * 1024];  // negated, same scheme
__device__ __align__(16) ull g_OutBZ[NCB * 512];   // (-ob, 0)
__device__ __align__(16) ull g_CbP  [NCB * 4096];  // (cbn[j][c], cbn[j+512][c])
__device__ __align__(16) ull g_Cs2  [NCB * 512];   // (-cs[j]/2, -cs[j+512]/2)

union F2u { ull u; float2 f; };
union F4u { float4 f; ull u[2]; };

__device__ __forceinline__ ull fma2(ull a, ull b, ull c) {
    ull d; asm("fma.rn.f32x2 %0, %1, %2, %3;" : "=l"(d) : "l"(a), "l"(b), "l"(c));
    return d;
}
__device__ __forceinline__ ull add2(ull a, ull b) {
    ull d; asm("add.rn.f32x2 %0, %1, %2;" : "=l"(d) : "l"(a), "l"(b));
    return d;
}
__device__ __forceinline__ ull dup2(float x) { F2u t; t.f.x = x; t.f.y = x; return t.u; }
__device__ __forceinline__ ull pk2(float a, float b) { F2u t; t.f.x = a; t.f.y = b; return t.u; }
__device__ __forceinline__ float lo2(ull a) { F2u t; t.u = a; return t.f.x; }
__device__ __forceinline__ float hi2(ull a) { F2u t; t.u = a; return t.f.y; }
__device__ __forceinline__ ull shfl64(ull v, int m) {
    return __shfl_xor_sync(0xffffffffu, v, m);
}
__device__ __forceinline__ unsigned f2s(float f) {
    unsigned u = __float_as_uint(f);
    unsigned s = (unsigned)((int)u >> 31);
    return u ^ (s | 0x80000000u);
}

// -------------------------- precompute kernel -----------------------------
__global__ void rvq_pre(const float* __restrict__ in_v,
                        const float* __restrict__ in_g,
                        const float* __restrict__ out_v,
                        const float* __restrict__ out_g,
                        const float* __restrict__ out_b,
                        const float* __restrict__ cb) {
    const int i = blockIdx.x;
    const int tid = threadIdx.x;          // 512 threads
    const int warp = tid >> 5, lane = tid & 31;
    __shared__ float nIn[8];

    // in_proj column norms over D (per channel c)
    if (warp < 8) {
        float s = 0.f;
        #pragma unroll
        for (int j = 0; j < 16; j++) {
            float v = in_v[i * 4096 + (lane + 32 * j) * 8 + warp];
            s += v * v;
        }
        #pragma unroll
        for (int off = 16; off >= 1; off >>= 1)
            s += __shfl_xor_sync(0xffffffffu, s, off);
        if (lane == 0) nIn[warp] = s;
    }
    __syncthreads();

    // W_in interleaved float4 planes
    {
        int dim = tid;
        float w[8];
        #pragma unroll
        for (int c = 0; c < 8; c++)
            w[c] = in_g[i * 8 + c] * in_v[i * 4096 + dim * 8 + c]
                   / fmaxf(sqrtf(nIn[c]), 1e-12f);
        g_Win4[(size_t)i * 1024 + dim]       = make_float4(w[0], w[1], w[2], w[3]);
        g_Win4[(size_t)i * 1024 + 512 + dim] = make_float4(w[4], w[5], w[6], w[7]);
    }

    // -W_out interleaved planes (norm over d = axis 0 of (d,D)); (-ob, 0) pairs
    {
        int dim = tid;
        float vv[8];
        float s = 0.f;
        #pragma unroll
        for (int c = 0; c < 8; c++) {
            vv[c] = out_v[i * 4096 + c * 512 + dim];
            s += vv[c] * vv[c];
        }
        float den = fmaxf(sqrtf(s), 1e-12f);
        float g = out_g[i * 512 + dim];
        #pragma unroll
        for (int c = 0; c < 8; c++) vv[c] = -(g * vv[c] / den);
        g_Wout4[(size_t)i * 1024 + dim]       = make_float4(vv[0], vv[1], vv[2], vv[3]);
        g_Wout4[(size_t)i * 1024 + 512 + dim] = make_float4(vv[4], vv[5], vv[6], vv[7]);
        g_OutBZ[i * 512 + dim] = pk2(-out_b[i * 512 + dim], 0.f);
    }

    // codebook: pack codeword-pairs (j, j+512) per channel, plus -cs/2 pairs
    {
        int j = tid;
        float a[8], b[8];
        float sa = 0.f, sb = 0.f;
        #pragma unroll
        for (int c = 0; c < 8; c++) {
            a[c] = cb[(size_t)i * 8192 + j * 8 + c];
            b[c] = cb[(size_t)i * 8192 + (j + 512) * 8 + c];
            sa += a[c] * a[c];
            sb += b[c] * b[c];
        }
        float da = fmaxf(sqrtf(sa), 1e-12f);
        float db = fmaxf(sqrtf(sb), 1e-12f);
        float csa = 0.f, csb = 0.f;
        #pragma unroll
        for (int c = 0; c < 8; c++) {
            float na = a[c] / da, nb = b[c] / db;
            g_CbP[(size_t)i * 4096 + j * 8 + c] = pk2(na, nb);
            csa += na * na;
            csb += nb * nb;
        }
        g_Cs2[i * 512 + j] = pk2(-0.5f * csa, -0.5f * csb);
    }
}

// ----------------------------- main kernel --------------------------------
__global__ __launch_bounds__(THREADS, 2)
void rvq_main(const float* __restrict__ z,
              const float* __restrict__ in_b,
              const float* __restrict__ codebooks,
              float* __restrict__ out) {
    extern __shared__ ull smU[];
    ull*    sEncD  = smU + U_ENCD;               // stride 10/token
    ull*    sCand  = smU + U_CAND;               // stride 9/token
    float*  smF    = (float*)smU;
    float*  sZq    = smF + F_ZQ;                 // ze then zq, stride 8/token
    float*  sLoss  = smF + F_LOSS;

    const int tid  = threadIdx.x;
    const int warp = tid >> 5;           // 0..7
    const int lane = tid & 31;
    const int tokBase = blockIdx.x * TOKPB;
    const int myT = lane >> 3;           // token-in-warp this lane owns
    const int myC = lane & 7;            // channel this lane owns
    const int wt  = warp * 4 + myT;      // block-local token of this lane

    // residual in registers: lane owns dims lane+32j for tokens warp*4+t
    float res[4][16];
    #pragma unroll
    for (int t = 0; t < 4; t++) {
        const float* zp = z + (size_t)(tokBase + warp * 4 + t) * DDIM + lane;
        #pragma unroll
        for (int j = 0; j < 16; j++) res[t][j] = zp[32 * j];
    }
    float lossAcc = 0.f;

    for (int i = 0; i < NCB; i++) {
        const float myInB = __ldg(in_b + i * 8 + myC);

        // ---- in_proj: weights direct from L1D (LDG.128 [base+imm]) ----
        {
            const float4* gwi = g_Win4 + (size_t)i * 1024 + lane;
            ull V[16];                        // V[t*4+p], p = channel pair
            #pragma unroll
            for (int q = 0; q < 16; q++) V[q] = 0;
            #pragma unroll
            for (int j = 0; j < 16; j++) {
                F4u wa, wb;
                wa.f = __ldg(gwi + 32 * j);            // ch 0-3
                wb.f = __ldg(gwi + 512 + 32 * j);      // ch 4-7
                #pragma unroll
                for (int t = 0; t < 4; t++) {
                    ull r = dup2(res[t][j]);
                    V[t * 4 + 0] = fma2(r, wa.u[0], V[t * 4 + 0]);
                    V[t * 4 + 1] = fma2(r, wa.u[1], V[t * 4 + 1]);
                    V[t * 4 + 2] = fma2(r, wb.u[0], V[t * 4 + 2]);
                    V[t * 4 + 3] = fma2(r, wb.u[1], V[t * 4 + 3]);
                }
            }
            // packed butterfly: 32 values over 32 lanes; lane ends with value=lane
            {
                bool h = (lane & 16);
                #pragma unroll
                for (int u = 0; u < 8; u++) {
                    ull a = h ? V[u + 8] : V[u];
                    ull b = h ? V[u] : V[u + 8];
                    V[u] = add2(a, shfl64(b, 16));
                }
            }
            {
                bool h = (lane & 8);
                #pragma unroll
                for (int u = 0; u < 4; u++) {
                    ull a = h ? V[u + 4] : V[u];
                    ull b = h ? V[u] : V[u + 4];
                    V[u] = add2(a, shfl64(b, 8));
                }
            }
            {
                bool h = (lane & 4);
                #pragma unroll
                for (int u = 0; u < 2; u++) {
                    ull a = h ? V[u + 2] : V[u];
                    ull b = h ? V[u] : V[u + 2];
                    V[u] = add2(a, shfl64(b, 4));
                }
            }
            {
                bool h = (lane & 2);
                ull a = h ? V[1] : V[0];
                ull b = h ? V[0] : V[1];
                V[0] = add2(a, shfl64(b, 2));
            }
            float val;
            {
                bool h = (lane & 1);
                float a = h ? hi2(V[0]) : lo2(V[0]);
                float b = h ? lo2(V[0]) : hi2(V[0]);
                val = a + __shfl_xor_sync(0xffffffffu, b, 1);
            }
            // lane = t*8 + c
            float ze = val + myInB;
            float s = ze * ze;
            s += __shfl_xor_sync(0xffffffffu, s, 1);
            s += __shfl_xor_sync(0xffffffffu, s, 2);
            s += __shfl_xor_sync(0xffffffffu, s, 4);
            float enc = ze / fmaxf(sqrtf(s), 1e-12f);
            sZq[wt * 8 + myC]    = ze;        // stash ze for finalize
            sEncD[wt * 10 + myC] = dup2(enc);
            out[OFF_LAT + (size_t)(tokBase + wt) * 72 + (size_t)i * 8 + myC] = ze;
        }
        __syncthreads();                       // enc-barrier

        // ---- NN search: codebook pairs direct from L1D/L2 ----
        {
            const int g = tid;
            const ull* cba = g_CbP + (size_t)i * 4096 + (size_t)g * 8;
            const ull* cbb = cba + 2048;           // row g+256
            ull cbA[8], cbB[8];
            #pragma unroll
            for (int q = 0; q < 2; q++) {
                F4u a0, a1, b0, b1;
                a0.f = __ldg((const float4*)(cba + 4 * q));
                a1.f = __ldg((const float4*)(cba + 4 * q + 2));
                b0.f = __ldg((const float4*)(cbb + 4 * q));
                b1.f = __ldg((const float4*)(cbb + 4 * q + 2));
                cbA[4 * q]     = a0.u[0]; cbA[4 * q + 1] = a0.u[1];
                cbA[4 * q + 2] = a1.u[0]; cbA[4 * q + 3] = a1.u[1];
                cbB[4 * q]     = b0.u[0]; cbB[4 * q + 1] = b0.u[1];
                cbB[4 * q + 2] = b1.u[0]; cbB[4 * q + 3] = b1.u[1];
            }
            const ull csA = __ldg(g_Cs2 + i * 512 + g);
            const ull csB = __ldg(g_Cs2 + i * 512 + g + 256);
            #pragma unroll 4
            for (int tt = 0; tt < TOKPB; tt++) {
                const float4* ep = (const float4*)(sEncD + tt * 10);
                F4u e0, e1, e2, e3;
                e0.f = ep[0]; e1.f = ep[1]; e2.f = ep[2]; e3.f = ep[3];
                ull dA = csA, dB = csB;
                dA = fma2(e0.u[0], cbA[0], dA); dB = fma2(e0.u[0], cbB[0], dB);
                dA = fma2(e0.u[1], cbA[1], dA); dB = fma2(e0.u[1], cbB[1], dB);
                dA = fma2(e1.u[0], cbA[2], dA); dB = fma2(e1.u[0], cbB[2], dB);
                dA = fma2(e1.u[1], cbA[3], dA); dB = fma2(e1.u[1], cbB[3], dB);
                dA = fma2(e2.u[0], cbA[4], dA); dB = fma2(e2.u[0], cbB[4], dB);
                dA = fma2(e2.u[1], cbA[5], dA); dB = fma2(e2.u[1], cbB[5], dB);
                dA = fma2(e3.u[0], cbA[6], dA); dB = fma2(e3.u[0], cbB[6], dB);
                dA = fma2(e3.u[1], cbA[7], dA); dB = fma2(e3.u[1], cbB[7], dB);
                // candidate order ascending index: g, g+256, g+512, g+768
                float best = lo2(dA); int bidx = g;
                float s1 = lo2(dB), s2 = hi2(dA), s3 = hi2(dB);
                if (s1 > best) { best = s1; bidx = g + 256; }
                if (s2 > best) { best = s2; bidx = g + 512; }
                if (s3 > best) { best = s3; bidx = g + 768; }
                unsigned bf = f2s(best);
                unsigned m = __reduce_max_sync(0xffffffffu, bf);
                int cand = (bf == m) ? bidx : 0x7fffffff;
                int kmin = __reduce_min_sync(0xffffffffu, cand);
                if (lane == 0)
                    sCand[tt * 9 + warp] = ((ull)m << 32) | (unsigned)(~kmin);
            }
        }
        __syncthreads();                       // cand-barrier

        // ---- finalize: warp-local, lane = myT*8+myC ----
        {
            ull best = sCand[wt * 9];
            #pragma unroll
            for (int w = 1; w < 8; w++) {
                ull k2 = sCand[wt * 9 + w];
                if (k2 > best) best = k2;          // max score, then min idx
            }
            unsigned kidx = ~(unsigned)best;
            int gtok = tokBase + wt;
            if (myC == 0)
                out[OFF_CODES + (size_t)gtok * NCB + i] = (float)kidx;
            float q = __ldg(codebooks + (size_t)i * 8192 + (size_t)kidx * 8 + myC);
            float ze = sZq[wt * 8 + myC];
            float zq = ze + (q - ze);              // straight-through
            float df = ze - q;
            lossAcc = fmaf(df, df, lossAcc);
            sZq[wt * 8 + myC] = zq;
            __syncwarp();
        }

        // ---- out_proj: weights direct from L1D; res += zq@(-W) + (-ob) ----
        {
            const float4* gwo = g_Wout4 + (size_t)i * 1024 + lane;
            const ull*    gbz = g_OutBZ + (size_t)i * 512 + lane;
            F4u a[4], b[4];
            #pragma unroll
            for (int t = 0; t < 4; t++) {
                int w2 = warp * 4 + t;
                a[t].f = *(const float4*)&sZq[w2 * 8];
                b[t].f = *(const float4*)&sZq[w2 * 8 + 4];
            }
            #pragma unroll
            for (int j = 0; j < 16; j++) {
                F4u wa, wb;
                wa.f = __ldg(gwo + 32 * j);
                wb.f = __ldg(gwo + 512 + 32 * j);
                ull nbz = __ldg(gbz + 32 * j);     // (-ob, 0)
                #pragma unroll
                for (int t = 0; t < 4; t++) {
                    ull p = fma2(a[t].u[0], wa.u[0], nbz);
                    p = fma2(a[t].u[1], wa.u[1], p);
                    p = fma2(b[t].u[0], wb.u[0], p);
                    p = fma2(b[t].u[1], wb.u[1], p);
                    res[t][j] += (lo2(p) + hi2(p));
                }
            }
        }
    }

    // ---- z_q = z - residual_final ----
    #pragma unroll
    for (int t = 0; t < 4; t++) {
        size_t base = (size_t)(tokBase + warp * 4 + t) * DDIM + lane;
        #pragma unroll
        for (int j = 0; j < 16; j++)
            out[base + 32 * j] = z[base + 32 * j] - res[t][j];
    }

    // ---- loss: warp reduce -> smem -> block reduce -> global ----
    {
        float s = lossAcc;
        #pragma unroll
        for (int off = 16; off >= 1; off >>= 1)
            s += __shfl_xor_sync(0xffffffffu, s, off);
        if (lane == 0) sLoss[warp] = s;
    }
    __syncthreads();
    if (tid == 0) {
        float s = 0.f;
        #pragma unroll
        for (int w = 0; w < 8; w++) s += sLoss[w];
        atomicAdd(&g_loss, (double)s);
        __threadfence();
        unsigned prev = atomicAdd(&g_done, 1u);
        if (prev == NBLOCKS - 1) {
            __threadfence();
            double L = g_loss;
            g_loss = 0.0;
            g_done = 0;
            float Lf = (float)(L * (1.0 / 524288.0));
            out[OFF_LOSS]     = Lf;
            out[OFF_LOSS + 1] = Lf;
        }
    }
}

// ------------------------------ launcher ----------------------------------
extern "C" void kernel_launch(void* const* d_in, const int* in_sizes, int n_in,
                              void* d_out, int out_size) {
    const float* z      = (const float*)d_in[0];
    const float* in_v   = (const float*)d_in[1];
    const float* in_g   = (const float*)d_in[2];
    const float* in_b   = (const float*)d_in[3];
    const float* out_v  = (const float*)d_in[4];
    const float* out_g  = (const float*)d_in[5];
    const float* out_b  = (const float*)d_in[6];
    const float* cbooks = (const float*)d_in[7];
    float* out = (float*)d_out;

    // Period-2 launch sequence: odd global launch indices are rvq_main,
    // so ncu's "-s 5 -c 1" lands on rvq_main.
    rvq_pre<<<NCB, 512>>>(in_v, in_g, out_v, out_g, out_b, cbooks);
    rvq_main<<<NBLOCKS, THREADS, SMEM_BYTES>>>(z, in_b, cbooks, out);
}

// round 14
// speedup vs baseline: 1.2841x; 1.2841x over previous
#include <cuda_runtime.h>
#include <cuda_bf16.h>

// ---------------------------------------------------------------------------
// ResidualVectorQuantize (eval mode), fp32 faithful, f32x2-packed, v11.
// B=16, T=4096, D=512, N=9, K=1024, d=8.
// Output layout (float32): [z_q (B*T*D)] [codes (B*T*N)] [latents (B*T*N*d)]
//                          [commitment_loss] [codebook_loss]
// v11 = v7 (best, 698us) + three surgical changes:
//   1. latents STG moved from in_proj (pre-barrier critical path) to finalize
//   2. NN codebook LDG burst issued BEFORE the weight-prefetch LDGSTS batch
//   3. sCand stride 9 -> 10 (16B-aligned rows, finalize uses 4x LDS.128)
// v8/v9/v10 experiments (cb cp.async, pre-barrier hoist, no-smem-weights)
// all REGRESSED and are reverted.
// ---------------------------------------------------------------------------

typedef unsigned long long ull;

#define BT   65536
#define DDIM 512
#define KCB  1024
#define NCB  9

#define OFF_CODES 33554432ull
#define OFF_LAT   34144256ull
#define OFF_LOSS  38862848ull

#define THREADS    256
#define TOKPB      32                  // tokens per block (4 per warp)
#define NBLOCKS    (BT / TOKPB)        // 2048

// smem layout, ull units:
#define U_WIN     0                    // float4[1024]: [dim]=ch0-3,[512+dim]=ch4-7
#define U_WOUT0   2048                 // float4[1024]: negated W_out, buf 0
#define U_WOUT1   4096                 // buf 1
#define U_OUTBZ0  6144                 // ull[512]: (-out_b, 0), buf 0
#define U_OUTBZ1  6656                 // buf 1
#define U_ENCD    7168                 // ull[320]: enc dup'd, stride 10/token
#define U_CAND    7488                 // ull[320]: stride 10/token (16B aligned)
#define U_TOTAL   7808
#define F_ZQ      (U_TOTAL * 2)        // float[256]: ze then zq, stride 8/token
#define F_INB     (F_ZQ + 256)         // float[72]: all 9 codebooks' in_b
#define F_LOSS    (F_INB + 72)         // float[8]
#define SMEM_BYTES ((F_LOSS + 8) * 4)  // 63808

// -------------------------- device scratch --------------------------------
__device__ double   g_loss = 0.0;
__device__ unsigned g_done = 0;
__device__ float4 g_Win4 [NCB * 1024];  // interleaved: [i*1024+dim], [..+512+dim]
__device__ float4 g_Wout4[NCB * 1024];  // negated, same scheme
__device__ __align__(16) ull g_OutBZ[NCB * 512];   // (-ob, 0)
__device__ __align__(16) ull g_CbP  [NCB * 4096];  // (cbn[j][c], cbn[j+512][c])
__device__ __align__(16) ull g_Cs2  [NCB * 512];   // (-cs[j]/2, -cs[j+512]/2)

union F2u { ull u; float2 f; };
union F4u { float4 f; ull u[2]; };

__device__ __forceinline__ ull fma2(ull a, ull b, ull c) {
    ull d; asm("fma.rn.f32x2 %0, %1, %2, %3;" : "=l"(d) : "l"(a), "l"(b), "l"(c));
    return d;
}
__device__ __forceinline__ ull add2(ull a, ull b) {
    ull d; asm("add.rn.f32x2 %0, %1, %2;" : "=l"(d) : "l"(a), "l"(b));
    return d;
}
__device__ __forceinline__ ull dup2(float x) { F2u t; t.f.x = x; t.f.y = x; return t.u; }
__device__ __forceinline__ ull pk2(float a, float b) { F2u t; t.f.x = a; t.f.y = b; return t.u; }
__device__ __forceinline__ float lo2(ull a) { F2u t; t.u = a; return t.f.x; }
__device__ __forceinline__ float hi2(ull a) { F2u t; t.u = a; return t.f.y; }
__device__ __forceinline__ ull umax64(ull a, ull b) { return a > b ? a : b; }
__device__ __forceinline__ ull shfl64(ull v, int m) {
    return __shfl_xor_sync(0xffffffffu, v, m);
}
__device__ __forceinline__ unsigned f2s(float f) {
    unsigned u = __float_as_uint(f);
    unsigned s = (unsigned)((int)u >> 31);
    return u ^ (s | 0x80000000u);
}
__device__ __forceinline__ unsigned smaddr(const void* p) {
    unsigned a;
    asm("{ .reg .u64 t; cvta.to.shared.u64 t, %1; cvt.u32.u64 %0, t; }"
        : "=r"(a) : "l"(p));
    return a;
}
__device__ __forceinline__ void cp16(unsigned dst, const void* src) {
    asm volatile("cp.async.cg.shared.global [%0], [%1], 16;"
                 :: "r"(dst), "l"(src));
}
#define CP_COMMIT() asm volatile("cp.async.commit_group;")
#define CP_WAIT0()  asm volatile("cp.async.wait_group 0;" ::: "memory")

// -------------------------- precompute kernel -----------------------------
__global__ void rvq_pre(const float* __restrict__ in_v,
                        const float* __restrict__ in_g,
                        const float* __restrict__ out_v,
                        const float* __restrict__ out_g,
                        const float* __restrict__ out_b,
                        const float* __restrict__ cb) {
    const int i = blockIdx.x;
    const int tid = threadIdx.x;          // 512 threads
    const int warp = tid >> 5, lane = tid & 31;
    __shared__ float nIn[8];

    // in_proj column norms over D (per channel c)
    if (warp < 8) {
        float s = 0.f;
        #pragma unroll
        for (int j = 0; j < 16; j++) {
            float v = in_v[i * 4096 + (lane + 32 * j) * 8 + warp];
            s += v * v;
        }
        #pragma unroll
        for (int off = 16; off >= 1; off >>= 1)
            s += __shfl_xor_sync(0xffffffffu, s, off);
        if (lane == 0) nIn[warp] = s;
    }
    __syncthreads();

    // W_in interleaved float4 planes
    {
        int dim = tid;
        float w[8];
        #pragma unroll
        for (int c = 0; c < 8; c++)
            w[c] = in_g[i * 8 + c] * in_v[i * 4096 + dim * 8 + c]
                   / fmaxf(sqrtf(nIn[c]), 1e-12f);
        g_Win4[(size_t)i * 1024 + dim]       = make_float4(w[0], w[1], w[2], w[3]);
        g_Win4[(size_t)i * 1024 + 512 + dim] = make_float4(w[4], w[5], w[6], w[7]);
    }

    // -W_out interleaved planes (norm over d = axis 0 of (d,D)); (-ob, 0) pairs
    {
        int dim = tid;
        float vv[8];
        float s = 0.f;
        #pragma unroll
        for (int c = 0; c < 8; c++) {
            vv[c] = out_v[i * 4096 + c * 512 + dim];
            s += vv[c] * vv[c];
        }
        float den = fmaxf(sqrtf(s), 1e-12f);
        float g = out_g[i * 512 + dim];
        #pragma unroll
        for (int c = 0; c < 8; c++) vv[c] = -(g * vv[c] / den);
        g_Wout4[(size_t)i * 1024 + dim]       = make_float4(vv[0], vv[1], vv[2], vv[3]);
        g_Wout4[(size_t)i * 1024 + 512 + dim] = make_float4(vv[4], vv[5], vv[6], vv[7]);
        g_OutBZ[i * 512 + dim] = pk2(-out_b[i * 512 + dim], 0.f);
    }

    // codebook: pack codeword-pairs (j, j+512) per channel, plus -cs/2 pairs
    {
        int j = tid;
        float a[8], b[8];
        float sa = 0.f, sb = 0.f;
        #pragma unroll
        for (int c = 0; c < 8; c++) {
            a[c] = cb[(size_t)i * 8192 + j * 8 + c];
            b[c] = cb[(size_t)i * 8192 + (j + 512) * 8 + c];
            sa += a[c] * a[c];
            sb += b[c] * b[c];
        }
        float da = fmaxf(sqrtf(sa), 1e-12f);
        float db = fmaxf(sqrtf(sb), 1e-12f);
        float csa = 0.f, csb = 0.f;
        #pragma unroll
        for (int c = 0; c < 8; c++) {
            float na = a[c] / da, nb = b[c] / db;
            g_CbP[(size_t)i * 4096 + j * 8 + c] = pk2(na, nb);
            csa += na * na;
            csb += nb * nb;
        }
        g_Cs2[i * 512 + j] = pk2(-0.5f * csa, -0.5f * csb);
    }
}

// ----------------------------- main kernel --------------------------------
__global__ __launch_bounds__(THREADS, 2)
void rvq_main(const float* __restrict__ z,
              const float* __restrict__ in_b,
              const float* __restrict__ codebooks,
              float* __restrict__ out) {
    extern __shared__ ull smU[];
    float4* sWin4  = (float4*)(smU + U_WIN);
    ull*    sEncD  = smU + U_ENCD;               // stride 10/token
    ull*    sCand  = smU + U_CAND;               // stride 10/token, 16B-aligned
    float*  smF    = (float*)smU;
    float*  sZq    = smF + F_ZQ;                 // ze then zq, stride 8/token
    float*  sInB   = smF + F_INB;                // all 9 iterations
    float*  sLoss  = smF + F_LOSS;

    const int tid  = threadIdx.x;
    const int warp = tid >> 5;           // 0..7
    const int lane = tid & 31;
    const int tokBase = blockIdx.x * TOKPB;
    const int myT = lane >> 3;           // token-in-warp this lane owns
    const int myC = lane & 7;            // channel this lane owns
    const int wt  = warp * 4 + myT;      // block-local token of this lane

    const unsigned aWin   = smaddr(smU + U_WIN);
    const unsigned aWout0 = smaddr(smU + U_WOUT0);
    const unsigned aWout1 = smaddr(smU + U_WOUT1);
    const unsigned aObz0  = smaddr(smU + U_OUTBZ0);
    const unsigned aObz1  = smaddr(smU + U_OUTBZ1);

    // residual in registers: lane owns dims lane+32j for tokens warp*4+t
    float res[4][16];
    #pragma unroll
    for (int t = 0; t < 4; t++) {
        const float* zp = z + (size_t)(tokBase + warp * 4 + t) * DDIM + lane;
        #pragma unroll
        for (int j = 0; j < 16; j++) res[t][j] = zp[32 * j];
    }
    float lossAcc = 0.f;

    // ---- prologue: stage iter-0 weights (buf 0) + all biases ----
    {
        #pragma unroll
        for (int r = 0; r < 4; r++) {
            cp16(aWin   + (unsigned)(tid + 256 * r) * 16, g_Win4  + tid + 256 * r);
            cp16(aWout0 + (unsigned)(tid + 256 * r) * 16, g_Wout4 + tid + 256 * r);
        }
        cp16(aObz0 + (unsigned)tid * 16, g_OutBZ + 2 * tid);
        CP_COMMIT();
        if (tid < 72) sInB[tid] = in_b[tid];
        CP_WAIT0();
        __syncthreads();
    }

    for (int i = 0; i < NCB; i++) {
        const float myInB = sInB[i * 8 + myC];

        // ---- in_proj: packed channel-pair accumulation, 4 tokens/warp ----
        {
            ull V[16];                        // V[t*4+p], p = channel pair
            #pragma unroll
            for (int q = 0; q < 16; q++) V[q] = 0;
            #pragma unroll
            for (int j = 0; j < 16; j++) {
                int dim = lane + 32 * j;
                F4u wa, wb;
                wa.f = sWin4[dim];            // ch 0-3
                wb.f = sWin4[dim + 512];      // ch 4-7
                #pragma unroll
                for (int t = 0; t < 4; t++) {
                    ull r = dup2(res[t][j]);
                    V[t * 4 + 0] = fma2(r, wa.u[0], V[t * 4 + 0]);
                    V[t * 4 + 1] = fma2(r, wa.u[1], V[t * 4 + 1]);
                    V[t * 4 + 2] = fma2(r, wb.u[0], V[t * 4 + 2]);
                    V[t * 4 + 3] = fma2(r, wb.u[1], V[t * 4 + 3]);
                }
            }
            // packed butterfly: 32 values over 32 lanes; lane ends with value=lane
            {
                bool h = (lane & 16);
                #pragma unroll
                for (int u = 0; u < 8; u++) {
                    ull a = h ? V[u + 8] : V[u];
                    ull b = h ? V[u] : V[u + 8];
                    V[u] = add2(a, shfl64(b, 16));
                }
            }
            {
                bool h = (lane & 8);
                #pragma unroll
                for (int u = 0; u < 4; u++) {
                    ull a = h ? V[u + 4] : V[u];
                    ull b = h ? V[u] : V[u + 4];
                    V[u] = add2(a, shfl64(b, 8));
                }
            }
            {
                bool h = (lane & 4);
                #pragma unroll
                for (int u = 0; u < 2; u++) {
                    ull a = h ? V[u + 2] : V[u];
                    ull b = h ? V[u] : V[u + 2];
                    V[u] = add2(a, shfl64(b, 4));
                }
            }
            {
                bool h = (lane & 2);
                ull a = h ? V[1] : V[0];
                ull b = h ? V[0] : V[1];
                V[0] = add2(a, shfl64(b, 2));
            }
            float val;
            {
                bool h = (lane & 1);
                float a = h ? hi2(V[0]) : lo2(V[0]);
                float b = h ? lo2(V[0]) : hi2(V[0]);
                val = a + __shfl_xor_sync(0xffffffffu, b, 1);
            }
            // lane = t*8 + c
            float ze = val + myInB;
            float s = ze * ze;
            s += __shfl_xor_sync(0xffffffffu, s, 1);
            s += __shfl_xor_sync(0xffffffffu, s, 2);
            s += __shfl_xor_sync(0xffffffffu, s, 4);
            float enc = ze / fmaxf(sqrtf(s), 1e-12f);
            sZq[wt * 8 + myC]    = ze;        // stash ze (latents stored later)
            sEncD[wt * 10 + myC] = dup2(enc);
        }
        __syncthreads();                       // enc-barrier

        // ---- NN codebook LDG burst FIRST (latency-critical for NN) ----
        ull cbA[8], cbB[8], csA, csB;
        {
            const int g = tid;
            const ull* cba = g_CbP + (size_t)i * 4096 + (size_t)g * 8;
            const ull* cbb = cba + 2048;           // row g+256
            #pragma unroll
            for (int q = 0; q < 2; q++) {
                F4u a0, a1, b0, b1;
                a0.f = __ldg((const float4*)(cba + 4 * q));
                a1.f = __ldg((const float4*)(cba + 4 * q + 2));
                b0.f = __ldg((const float4*)(cbb + 4 * q));
                b1.f = __ldg((const float4*)(cbb + 4 * q + 2));
                cbA[4 * q]     = a0.u[0]; cbA[4 * q + 1] = a0.u[1];
                cbA[4 * q + 2] = a1.u[0]; cbA[4 * q + 3] = a1.u[1];
                cbB[4 * q]     = b0.u[0]; cbB[4 * q + 1] = b0.u[1];
                cbB[4 * q + 2] = b1.u[0]; cbB[4 * q + 3] = b1.u[1];
            }
            csA = __ldg(g_Cs2 + i * 512 + g);
            csB = __ldg(g_Cs2 + i * 512 + g + 256);
        }

        // ---- weight prefetch for i+1 AFTER cb loads (LSU ordering) ----
        if (i < NCB - 1) {
            const float4* gw = g_Win4  + (size_t)(i + 1) * 1024;
            const float4* go = g_Wout4 + (size_t)(i + 1) * 1024;
            const ull*    gb = g_OutBZ + (size_t)(i + 1) * 512;
            unsigned aWoutN = ((i + 1) & 1) ? aWout1 : aWout0;
            unsigned aObzN  = ((i + 1) & 1) ? aObz1  : aObz0;
            #pragma unroll
            for (int r = 0; r < 4; r++) {
                cp16(aWin   + (unsigned)(tid + 256 * r) * 16, gw + tid + 256 * r);
                cp16(aWoutN + (unsigned)(tid + 256 * r) * 16, go + tid + 256 * r);
            }
            cp16(aObzN + (unsigned)tid * 16, gb + 2 * tid);
            CP_COMMIT();
        }

        // ---- NN search: register-resident codebook ----
        {
            const int g = tid;
            #pragma unroll 4
            for (int tt = 0; tt < TOKPB; tt++) {
                const float4* ep = (const float4*)(sEncD + tt * 10);
                F4u e0, e1, e2, e3;
                e0.f = ep[0]; e1.f = ep[1]; e2.f = ep[2]; e3.f = ep[3];
                ull dA = csA, dB = csB;
                dA = fma2(e0.u[0], cbA[0], dA); dB = fma2(e0.u[0], cbB[0], dB);
                dA = fma2(e0.u[1], cbA[1], dA); dB = fma2(e0.u[1], cbB[1], dB);
                dA = fma2(e1.u[0], cbA[2], dA); dB = fma2(e1.u[0], cbB[2], dB);
                dA = fma2(e1.u[1], cbA[3], dA); dB = fma2(e1.u[1], cbB[3], dB);
                dA = fma2(e2.u[0], cbA[4], dA); dB = fma2(e2.u[0], cbB[4], dB);
                dA = fma2(e2.u[1], cbA[5], dA); dB = fma2(e2.u[1], cbB[5], dB);
                dA = fma2(e3.u[0], cbA[6], dA); dB = fma2(e3.u[0], cbB[6], dB);
                dA = fma2(e3.u[1], cbA[7], dA); dB = fma2(e3.u[1], cbB[7], dB);
                // candidate order ascending index: g, g+256, g+512, g+768
                float best = lo2(dA); int bidx = g;
                float s1 = lo2(dB), s2 = hi2(dA), s3 = hi2(dB);
                if (s1 > best) { best = s1; bidx = g + 256; }
                if (s2 > best) { best = s2; bidx = g + 512; }
                if (s3 > best) { best = s3; bidx = g + 768; }
                unsigned bf = f2s(best);
                unsigned m = __reduce_max_sync(0xffffffffu, bf);
                int cand = (bf == m) ? bidx : 0x7fffffff;
                int kmin = __reduce_min_sync(0xffffffffu, cand);
                if (lane == 0)
                    sCand[tt * 10 + warp] = ((ull)m << 32) | (unsigned)(~kmin);
            }
        }
        CP_WAIT0();                            // weights(i+1) staged
        __syncthreads();                       // cand-barrier

        // ---- finalize: warp-local, lane = myT*8+myC; latents stored here ----
        {
            const ull* cr = sCand + wt * 10;   // 16B-aligned row
            F4u q0, q1, q2, q3;
            q0.f = *(const float4*)(cr);
            q1.f = *(const float4*)(cr + 2);
            q2.f = *(const float4*)(cr + 4);
            q3.f = *(const float4*)(cr + 6);
            ull best = umax64(umax64(umax64(q0.u[0], q0.u[1]),
                                     umax64(q1.u[0], q1.u[1])),
                              umax64(umax64(q2.u[0], q2.u[1]),
                                     umax64(q3.u[0], q3.u[1])));
            unsigned kidx = ~(unsigned)best;
            int gtok = tokBase + wt;
            if (myC == 0)
                out[OFF_CODES + (size_t)gtok * NCB + i] = (float)kidx;
            float q = __ldg(codebooks + (size_t)i * 8192 + (size_t)kidx * 8 + myC);
            float ze = sZq[wt * 8 + myC];
            out[OFF_LAT + (size_t)gtok * 72 + (size_t)i * 8 + myC] = ze;
            float zq = ze + (q - ze);              // straight-through
            float df = ze - q;
            lossAcc = fmaf(df, df, lossAcc);
            sZq[wt * 8 + myC] = zq;
            __syncwarp();
        }

        // ---- out_proj: res += zq @ (-W_out) + (-out_b)  (4 tokens/warp) ----
        {
            const float4* sWoutC = (float4*)(smU + ((i & 1) ? U_WOUT1 : U_WOUT0));
            const ull*    sObzC  = smU + ((i & 1) ? U_OUTBZ1 : U_OUTBZ0);
            F4u a[4], b[4];
            #pragma unroll
            for (int t = 0; t < 4; t++) {
                int w2 = warp * 4 + t;
                a[t].f = *(const float4*)&sZq[w2 * 8];
                b[t].f = *(const float4*)&sZq[w2 * 8 + 4];
            }
            #pragma unroll
            for (int j = 0; j < 16; j++) {
                int dim = lane + 32 * j;
                F4u wa, wb;
                wa.f = sWoutC[dim];
                wb.f = sWoutC[dim + 512];
                ull nbz = sObzC[dim];              // (-ob, 0)
                #pragma unroll
                for (int t = 0; t < 4; t++) {
                    ull p = fma2(a[t].u[0], wa.u[0], nbz);
                    p = fma2(a[t].u[1], wa.u[1], p);
                    p = fma2(b[t].u[0], wb.u[0], p);
                    p = fma2(b[t].u[1], wb.u[1], p);
                    res[t][j] += (lo2(p) + hi2(p));
                }
            }
        }
    }

    // ---- z_q = z - residual_final ----
    #pragma unroll
    for (int t = 0; t < 4; t++) {
        size_t base = (size_t)(tokBase + warp * 4 + t) * DDIM + lane;
        #pragma unroll
        for (int j = 0; j < 16; j++)
            out[base + 32 * j] = z[base + 32 * j] - res[t][j];
    }

    // ---- loss: warp reduce -> smem -> block reduce -> global ----
    {
        float s = lossAcc;
        #pragma unroll
        for (int off = 16; off >= 1; off >>= 1)
            s += __shfl_xor_sync(0xffffffffu, s, off);
        if (lane == 0) sLoss[warp] = s;
    }
    __syncthreads();
    if (tid == 0) {
        float s = 0.f;
        #pragma unroll
        for (int w = 0; w < 8; w++) s += sLoss[w];
        atomicAdd(&g_loss, (double)s);
        __threadfence();
        unsigned prev = atomicAdd(&g_done, 1u);
        if (prev == NBLOCKS - 1) {
            __threadfence();
            double L = g_loss;
            g_loss = 0.0;
            g_done = 0;
            float Lf = (float)(L * (1.0 / 524288.0));
            out[OFF_LOSS]     = Lf;
            out[OFF_LOSS + 1] = Lf;
        }
    }
}

// ------------------------------ launcher ----------------------------------
extern "C" void kernel_launch(void* const* d_in, const int* in_sizes, int n_in,
                              void* d_out, int out_size) {
    const float* z      = (const float*)d_in[0];
    const float* in_v   = (const float*)d_in[1];
    const float* in_g   = (const float*)d_in[2];
    const float* in_b   = (const float*)d_in[3];
    const float* out_v  = (const float*)d_in[4];
    const float* out_g  = (const float*)d_in[5];
    const float* out_b  = (const float*)d_in[6];
    const float* cbooks = (const float*)d_in[7];
    float* out = (float*)d_out;

    cudaFuncSetAttribute(rvq_main, cudaFuncAttributeMaxDynamicSharedMemorySize,
                         SMEM_BYTES);

    // Period-2 launch sequence: odd global launch indices are rvq_main,
    // so ncu's "-s 5 -c 1" lands on rvq_main.
    rvq_pre<<<NCB, 512>>>(in_v, in_g, out_v, out_g, out_b, cbooks);
    rvq_main<<<NBLOCKS, THREADS, SMEM_BYTES>>>(z, in_b, cbooks, out);
}